// round 2
// baseline (speedup 1.0000x reference)
#include <cuda_runtime.h>
#include <cstdint>

#define N_NODES  50000
#define N_EDGES  800000
#define D_IN     128
#define D_HID    256
#define N_GRAPHS 256

// ---------------- scratch (device globals; no runtime allocation) ----------------
__device__ float g_agg1[N_NODES * D_IN];     // 25.6 MB
__device__ float g_h1  [N_NODES * D_HID];    // 51.2 MB
__device__ float g_agg2[N_NODES * D_HID];    // 51.2 MB
__device__ float g_h2  [N_NODES * D_HID];    // 51.2 MB
__device__ int   g_cnt [N_NODES];            // in-degree histogram
__device__ int   g_row [N_NODES + 1];        // CSR row pointers
__device__ int   g_cur [N_NODES];            // fill cursors
__device__ int   g_col [N_EDGES];            // CSR column (src) ids
__device__ int   g_idx64;                    // 1 if indices are int64, 0 if int32

// ---------------- dtype detection ----------------
// int64 little-endian with values < 2^31: every odd 32-bit word of the first
// 128 entries is zero. For random int32 indices that is (effectively) impossible.
__global__ void detect_kernel(const int* __restrict__ ei) {
    int any = 0;
#pragma unroll
    for (int i = 1; i < 256; i += 2) any |= ei[i];
    g_idx64 = (any == 0) ? 1 : 0;
}

__device__ __forceinline__ int load_idx(const void* p, int i) {
    if (g_idx64) return (int)((const long long*)p)[i];
    return ((const int*)p)[i];
}

// ---------------- CSR build ----------------
__global__ void zero_cnt_kernel() {
    int i = blockIdx.x * blockDim.x + threadIdx.x;
    int stride = gridDim.x * blockDim.x;
    for (; i < N_NODES; i += stride) g_cnt[i] = 0;
}

__global__ void hist_kernel(const void* __restrict__ ei) {
    int i = blockIdx.x * blockDim.x + threadIdx.x;
    int stride = gridDim.x * blockDim.x;
    for (; i < N_EDGES; i += stride) {
        int d = load_idx(ei, i + N_EDGES);   // dst row
        atomicAdd(&g_cnt[d], 1);
    }
}

#define SCAN_T 1024
__global__ void scan_kernel() {
    __shared__ int part[SCAN_T];
    int t = threadIdx.x;
    const int C = (N_NODES + SCAN_T - 1) / SCAN_T;   // 49
    int lo = t * C;
    int hi = lo + C; if (hi > N_NODES) hi = N_NODES;
    int s = 0;
    for (int i = lo; i < hi; i++) s += g_cnt[i];
    part[t] = s;
    __syncthreads();
    // inclusive Hillis-Steele scan
    for (int off = 1; off < SCAN_T; off <<= 1) {
        int v = (t >= off) ? part[t - off] : 0;
        __syncthreads();
        part[t] += v;
        __syncthreads();
    }
    int run = (t == 0) ? 0 : part[t - 1];   // exclusive prefix
    for (int i = lo; i < hi; i++) {
        g_row[i] = run;
        g_cur[i] = run;
        run += g_cnt[i];
    }
    if (t == SCAN_T - 1) g_row[N_NODES] = run;
}

__global__ void fill_kernel(const void* __restrict__ ei) {
    int i = blockIdx.x * blockDim.x + threadIdx.x;
    int stride = gridDim.x * blockDim.x;
    for (; i < N_EDGES; i += stride) {
        int s = load_idx(ei, i);
        int d = load_idx(ei, i + N_EDGES);
        int pos = atomicAdd(&g_cur[d], 1);
        g_col[pos] = s;
    }
}

// ---------------- deterministic gather aggregation ----------------
// One warp per destination node; lanes cover the feature dim in float4s.
template<int D>
__global__ void gather_agg(const float* __restrict__ x, float* __restrict__ agg) {
    int warp = (blockIdx.x * blockDim.x + threadIdx.x) >> 5;
    if (warp >= N_NODES) return;
    int lane = threadIdx.x & 31;
    int beg = g_row[warp], end = g_row[warp + 1];
    if (D == 128) {
        float4 a = make_float4(0.f, 0.f, 0.f, 0.f);
        for (int p = beg; p < end; p++) {
            int s = g_col[p];
            float4 v = ((const float4*)x)[(size_t)s * 32 + lane];
            a.x += v.x; a.y += v.y; a.z += v.z; a.w += v.w;
        }
        ((float4*)agg)[(size_t)warp * 32 + lane] = a;
    } else {
        float4 a0 = make_float4(0.f, 0.f, 0.f, 0.f);
        float4 a1 = make_float4(0.f, 0.f, 0.f, 0.f);
        for (int p = beg; p < end; p++) {
            int s = g_col[p];
            const float4* xp = (const float4*)x + (size_t)s * 64;
            float4 v0 = xp[lane];
            float4 v1 = xp[lane + 32];
            a0.x += v0.x; a0.y += v0.y; a0.z += v0.z; a0.w += v0.w;
            a1.x += v1.x; a1.y += v1.y; a1.z += v1.z; a1.w += v1.w;
        }
        float4* ap = (float4*)agg + (size_t)warp * 64;
        ap[lane] = a0;
        ap[lane + 32] = a1;
    }
}

// ---------------- fused dual GEMM + bias + relu ----------------
// C[m, n] = relu( sum_k A1[m,k]*W1[n,k] + sum_k A2[m,k]*W2[n,k] + bias[n] )
template<int K>
__global__ __launch_bounds__(256) void gemm_dual_relu(
    const float* __restrict__ A1, const float* __restrict__ W1,
    const float* __restrict__ A2, const float* __restrict__ W2,
    const float* __restrict__ bias, float* __restrict__ C) {
    constexpr int BM = 128, BN = 64, BK = 32;
    __shared__ float As[BK][BM];
    __shared__ float Bs[BK][BN];
    int tid = threadIdx.x;
    int tx = tid & 15;   // N dim: 16 * 4 = 64
    int ty = tid >> 4;   // M dim: 16 * 8 = 128
    int bm = blockIdx.x * BM;
    int bn = blockIdx.y * BN;

    float acc[8][4] = {};

#pragma unroll 1
    for (int phase = 0; phase < 2; phase++) {
        const float* A = phase ? A2 : A1;
        const float* W = phase ? W2 : W1;
#pragma unroll 1
        for (int k0 = 0; k0 < K; k0 += BK) {
#pragma unroll
            for (int i = 0; i < 4; i++) {
                int t  = tid + i * 256;
                int m  = t >> 3;
                int kv = (t & 7) * 4;
                float4 v = make_float4(0.f, 0.f, 0.f, 0.f);
                int row = bm + m;
                if (row < N_NODES)
                    v = *(const float4*)(A + (size_t)row * K + k0 + kv);
                As[kv + 0][m] = v.x; As[kv + 1][m] = v.y;
                As[kv + 2][m] = v.z; As[kv + 3][m] = v.w;
            }
#pragma unroll
            for (int i = 0; i < 2; i++) {
                int t  = tid + i * 256;
                int n  = t >> 3;
                int kv = (t & 7) * 4;
                float4 v = *(const float4*)(W + (size_t)(bn + n) * K + k0 + kv);
                Bs[kv + 0][n] = v.x; Bs[kv + 1][n] = v.y;
                Bs[kv + 2][n] = v.z; Bs[kv + 3][n] = v.w;
            }
            __syncthreads();
#pragma unroll
            for (int k = 0; k < BK; k++) {
                float4 a0 = *(const float4*)&As[k][ty * 8];
                float4 a1 = *(const float4*)&As[k][ty * 8 + 4];
                float4 b0 = *(const float4*)&Bs[k][tx * 4];
                float a[8] = {a0.x, a0.y, a0.z, a0.w, a1.x, a1.y, a1.z, a1.w};
                float b[4] = {b0.x, b0.y, b0.z, b0.w};
#pragma unroll
                for (int i = 0; i < 8; i++)
#pragma unroll
                    for (int j = 0; j < 4; j++)
                        acc[i][j] = fmaf(a[i], b[j], acc[i][j]);
            }
            __syncthreads();
        }
    }

    float4 bb = *(const float4*)(bias + bn + tx * 4);
#pragma unroll
    for (int i = 0; i < 8; i++) {
        int row = bm + ty * 8 + i;
        if (row < N_NODES) {
            float4 o;
            o.x = fmaxf(acc[i][0] + bb.x, 0.f);
            o.y = fmaxf(acc[i][1] + bb.y, 0.f);
            o.z = fmaxf(acc[i][2] + bb.z, 0.f);
            o.w = fmaxf(acc[i][3] + bb.w, 0.f);
            *(float4*)(C + (size_t)row * D_HID + bn + tx * 4) = o;
        }
    }
}

// ---------------- fused mean-pool + FC + sigmoid (deterministic) ----------------
// batch is sorted, so graph g owns a contiguous node range found by binary search.
__global__ void poolfc_kernel(const float* __restrict__ h, const void* __restrict__ batch,
                              const float* __restrict__ Wfc, const float* __restrict__ bfc,
                              float* __restrict__ out) {
    int g = blockIdx.x;
    int t = threadIdx.x;

    // lower_bound(g) and lower_bound(g+1) over sorted batch
    int start, end;
    {
        int lo = 0, hi = N_NODES;
        while (lo < hi) { int mid = (lo + hi) >> 1; if (load_idx(batch, mid) < g) lo = mid + 1; else hi = mid; }
        start = lo;
        lo = start; hi = N_NODES;
        while (lo < hi) { int mid = (lo + hi) >> 1; if (load_idx(batch, mid) < g + 1) lo = mid + 1; else hi = mid; }
        end = lo;
    }

    float s = 0.f;
    for (int n = start; n < end; n++)
        s += h[(size_t)n * D_HID + t];
    float inv = 1.0f / fmaxf((float)(end - start), 1.0f);
    float p = s * inv;

    __shared__ float r0[256], r1[256];
    r0[t] = p * Wfc[t];
    r1[t] = p * Wfc[D_HID + t];
    __syncthreads();
    for (int off = 128; off > 0; off >>= 1) {
        if (t < off) { r0[t] += r0[t + off]; r1[t] += r1[t + off]; }
        __syncthreads();
    }
    if (t == 0) {
        out[g * 2 + 0] = 1.0f / (1.0f + expf(-(r0[0] + bfc[0])));
        out[g * 2 + 1] = 1.0f / (1.0f + expf(-(r1[0] + bfc[1])));
    }
}

// ---------------- launch ----------------
extern "C" void kernel_launch(void* const* d_in, const int* in_sizes, int n_in,
                              void* d_out, int out_size) {
    const float* x  = (const float*)d_in[0];
    const void*  ei = d_in[1];
    const void*  bt = d_in[2];
    int wbase = (n_in >= 12 && in_sizes[3] == 1) ? 4 : 3;
    const float* W1_root = (const float*)d_in[wbase + 0];
    const float* W1_rel  = (const float*)d_in[wbase + 1];
    const float* b1      = (const float*)d_in[wbase + 2];
    const float* W2_root = (const float*)d_in[wbase + 3];
    const float* W2_rel  = (const float*)d_in[wbase + 4];
    const float* b2      = (const float*)d_in[wbase + 5];
    const float* Wfc     = (const float*)d_in[wbase + 6];
    const float* bfc     = (const float*)d_in[wbase + 7];
    float* out = (float*)d_out;

    // CSR build (ints only)
    detect_kernel<<<1, 1>>>((const int*)ei);
    zero_cnt_kernel<<<200, 256>>>();
    hist_kernel<<<1024, 256>>>(ei);
    scan_kernel<<<1, SCAN_T>>>();
    fill_kernel<<<1024, 256>>>(ei);

    // Layer 1
    {
        int warps_total = N_NODES;
        int blocks = (warps_total * 32 + 255) / 256;
        gather_agg<D_IN><<<blocks, 256>>>(x, g_agg1);
        dim3 grid((N_NODES + 127) / 128, D_HID / 64);
        gemm_dual_relu<D_IN><<<grid, 256>>>(x, W1_root, g_agg1, W1_rel, b1, g_h1);
    }

    // Layer 2
    {
        int warps_total = N_NODES;
        int blocks = (warps_total * 32 + 255) / 256;
        gather_agg<D_HID><<<blocks, 256>>>(g_h1, g_agg2);
        dim3 grid((N_NODES + 127) / 128, D_HID / 64);
        gemm_dual_relu<D_HID><<<grid, 256>>>(g_h1, W2_root, g_agg2, W2_rel, b2, g_h2);
    }

    // Pool + FC + sigmoid (deterministic, no atomics)
    poolfc_kernel<<<N_GRAPHS, 256>>>(g_h2, bt, Wfc, bfc, out);
    (void)out_size;
}

// round 3
// speedup vs baseline: 1.1180x; 1.1180x over previous
#include <cuda_runtime.h>
#include <cstdint>

#define N_NODES  50000
#define N_EDGES  800000
#define D_IN     128
#define D_HID    256
#define N_GRAPHS 256

typedef unsigned long long ull;

// ---------------- scratch (device globals; no runtime allocation) ----------------
__device__ float g_agg1[N_NODES * D_IN];     // 25.6 MB
__device__ float g_h1  [N_NODES * D_HID];    // 51.2 MB
__device__ float g_agg2[N_NODES * D_HID];    // 51.2 MB
__device__ float g_h2  [N_NODES * D_HID];    // 51.2 MB
__device__ int   g_cnt [N_NODES];            // in-degree histogram
__device__ int   g_row [N_NODES + 1];        // CSR row pointers
__device__ int   g_cur [N_NODES];            // fill cursors
__device__ int   g_col [N_EDGES];            // CSR column (src) ids
__device__ int   g_bsum[64];                 // block partial sums for scan
__device__ int   g_idx64;                    // 1 if indices are int64, 0 if int32

// ---------------- packed f32x2 helpers ----------------
__device__ __forceinline__ ull pack2(float lo, float hi) {
    ull r;
    asm("mov.b64 %0, {%1, %2};" : "=l"(r) : "f"(lo), "f"(hi));
    return r;
}
__device__ __forceinline__ void unpack2(ull v, float& lo, float& hi) {
    asm("mov.b64 {%0, %1}, %2;" : "=f"(lo), "=f"(hi) : "l"(v));
}
__device__ __forceinline__ ull fma2(ull a, ull b, ull c) {
    ull r;
    asm("fma.rn.f32x2 %0, %1, %2, %3;" : "=l"(r) : "l"(a), "l"(b), "l"(c));
    return r;
}

// ---------------- dtype detection ----------------
__global__ void detect_kernel(const int* __restrict__ ei) {
    int any = 0;
#pragma unroll
    for (int i = 1; i < 256; i += 2) any |= ei[i];
    g_idx64 = (any == 0) ? 1 : 0;
}

__device__ __forceinline__ int load_idx(const void* p, int i) {
    if (g_idx64) return (int)((const long long*)p)[i];
    return ((const int*)p)[i];
}

// ---------------- CSR build ----------------
__global__ void zero_cnt_kernel() {
    int i = blockIdx.x * blockDim.x + threadIdx.x;
    int stride = gridDim.x * blockDim.x;
    for (; i < N_NODES; i += stride) g_cnt[i] = 0;
}

__global__ void hist_kernel(const void* __restrict__ ei) {
    int i = blockIdx.x * blockDim.x + threadIdx.x;
    int stride = gridDim.x * blockDim.x;
    for (; i < N_EDGES; i += stride) {
        int d = load_idx(ei, i + N_EDGES);
        atomicAdd(&g_cnt[d], 1);
    }
}

#define SCAN_B 49   // ceil(50000/1024)
// per-block exclusive scan; local prefix into g_row, block total into g_bsum
__global__ void scan_blk_kernel() {
    __shared__ int wsum[32];
    int b = blockIdx.x, t = threadIdx.x;
    int i = b * 1024 + t;
    int v = (i < N_NODES) ? g_cnt[i] : 0;
    int lane = t & 31, w = t >> 5;
    int s = v;
#pragma unroll
    for (int o = 1; o < 32; o <<= 1) {
        int u = __shfl_up_sync(0xffffffffu, s, o);
        if (lane >= o) s += u;
    }
    if (lane == 31) wsum[w] = s;
    __syncthreads();
    if (w == 0) {
        int ws = (lane < 32) ? wsum[lane] : 0;
#pragma unroll
        for (int o = 1; o < 32; o <<= 1) {
            int u = __shfl_up_sync(0xffffffffu, ws, o);
            if (lane >= o) ws += u;
        }
        wsum[lane] = ws;
    }
    __syncthreads();
    int incl = s + (w > 0 ? wsum[w - 1] : 0);
    if (i < N_NODES) g_row[i] = incl - v;      // local exclusive prefix
    if (t == 1023) g_bsum[b] = incl;           // block total (inclusive of all)
}

__global__ void scan_top_kernel() {
    if (threadIdx.x == 0) {
        int run = 0;
        for (int b = 0; b < SCAN_B; b++) { int v = g_bsum[b]; g_bsum[b] = run; run += v; }
    }
}

__global__ void scan_add_kernel() {
    int b = blockIdx.x, t = threadIdx.x;
    int i = b * 1024 + t;
    if (i < N_NODES) {
        int r = g_row[i] + g_bsum[b];
        g_row[i] = r;
        g_cur[i] = r;
    }
    if (i == 0) g_row[N_NODES] = N_EDGES;
}

__global__ void fill_kernel(const void* __restrict__ ei) {
    int i = blockIdx.x * blockDim.x + threadIdx.x;
    int stride = gridDim.x * blockDim.x;
    for (; i < N_EDGES; i += stride) {
        int s = load_idx(ei, i);
        int d = load_idx(ei, i + N_EDGES);
        int pos = atomicAdd(&g_cur[d], 1);
        g_col[pos] = s;
    }
}

// ---------------- deterministic gather aggregation ----------------
// One warp per destination node; unrolled x2 for memory-level parallelism.
template<int D>
__global__ void gather_agg(const float* __restrict__ x, float* __restrict__ agg) {
    int warp = (blockIdx.x * blockDim.x + threadIdx.x) >> 5;
    if (warp >= N_NODES) return;
    int lane = threadIdx.x & 31;
    int beg = g_row[warp], end = g_row[warp + 1];
    constexpr int V = D / 128;   // float4s per lane (1 or 2)
    float4 a[V];
#pragma unroll
    for (int v = 0; v < V; v++) a[v] = make_float4(0.f, 0.f, 0.f, 0.f);
    int p = beg;
    for (; p + 2 <= end; p += 2) {
        int s0 = g_col[p], s1 = g_col[p + 1];
        const float4* x0 = (const float4*)x + (size_t)s0 * (D / 4);
        const float4* x1 = (const float4*)x + (size_t)s1 * (D / 4);
        float4 v0[V], v1[V];
#pragma unroll
        for (int v = 0; v < V; v++) { v0[v] = x0[lane + v * 32]; v1[v] = x1[lane + v * 32]; }
#pragma unroll
        for (int v = 0; v < V; v++) {
            a[v].x += v0[v].x + v1[v].x; a[v].y += v0[v].y + v1[v].y;
            a[v].z += v0[v].z + v1[v].z; a[v].w += v0[v].w + v1[v].w;
        }
    }
    if (p < end) {
        int s0 = g_col[p];
        const float4* x0 = (const float4*)x + (size_t)s0 * (D / 4);
#pragma unroll
        for (int v = 0; v < V; v++) {
            float4 v0 = x0[lane + v * 32];
            a[v].x += v0.x; a[v].y += v0.y; a[v].z += v0.z; a[v].w += v0.w;
        }
    }
    float4* ap = (float4*)agg + (size_t)warp * (D / 4);
#pragma unroll
    for (int v = 0; v < V; v++) ap[lane + v * 32] = a[v];
}

// ---------------- fused dual GEMM + bias + relu (f32x2 packed FMA) ----------------
// C[m,n] = relu( sum_k A1[m,k]W1[n,k] + sum_k A2[m,k]W2[n,k] + bias[n] )
// BM=128, BN=128, BK=16, 256 threads, 8x8 microtile (acc packed in pairs along N).
#define PADW 132
template<int K>
__global__ __launch_bounds__(256) void gemm_dual_relu(
    const float* __restrict__ A1, const float* __restrict__ W1,
    const float* __restrict__ A2, const float* __restrict__ W2,
    const float* __restrict__ bias, float* __restrict__ C) {
    constexpr int BK = 16;
    constexpr int T = K / BK;         // tiles per phase
    __shared__ float As[2][BK][PADW];
    __shared__ float Bs[2][BK][PADW];

    int tid = threadIdx.x;
    int tx = tid & 15;                // n: 16*8 = 128
    int ty = tid >> 4;                // m: 16*8 = 128
    int bm = blockIdx.x * 128;
    int bn = blockIdx.y * 128;

    int lm = tid >> 2;                // 0..63 (row within tile)
    int lk = (tid & 3) * 4;           // 0,4,8,12 (k start)

    ull acc[8][4];
#pragma unroll
    for (int i = 0; i < 8; i++)
#pragma unroll
        for (int j = 0; j < 4; j++) acc[i][j] = pack2(0.f, 0.f);

    const float4 z4 = make_float4(0.f, 0.f, 0.f, 0.f);

#pragma unroll 1
    for (int phase = 0; phase < 2; phase++) {
        const float* A = phase ? A2 : A1;
        const float* W = phase ? W2 : W1;

        // prologue: load tile 0 -> regs -> smem[0]
        float4 ra0, ra1, rb0, rb1;
        {
            int r0 = bm + lm, r1 = bm + lm + 64;
            ra0 = (r0 < N_NODES) ? *(const float4*)(A + (size_t)r0 * K + lk) : z4;
            ra1 = (r1 < N_NODES) ? *(const float4*)(A + (size_t)r1 * K + lk) : z4;
            rb0 = *(const float4*)(W + (size_t)(bn + lm) * K + lk);
            rb1 = *(const float4*)(W + (size_t)(bn + lm + 64) * K + lk);
            As[0][lk + 0][lm] = ra0.x; As[0][lk + 1][lm] = ra0.y;
            As[0][lk + 2][lm] = ra0.z; As[0][lk + 3][lm] = ra0.w;
            As[0][lk + 0][lm + 64] = ra1.x; As[0][lk + 1][lm + 64] = ra1.y;
            As[0][lk + 2][lm + 64] = ra1.z; As[0][lk + 3][lm + 64] = ra1.w;
            Bs[0][lk + 0][lm] = rb0.x; Bs[0][lk + 1][lm] = rb0.y;
            Bs[0][lk + 2][lm] = rb0.z; Bs[0][lk + 3][lm] = rb0.w;
            Bs[0][lk + 0][lm + 64] = rb1.x; Bs[0][lk + 1][lm + 64] = rb1.y;
            Bs[0][lk + 2][lm + 64] = rb1.z; Bs[0][lk + 3][lm + 64] = rb1.w;
        }
        __syncthreads();

#pragma unroll 1
        for (int t = 0; t < T; t++) {
            int cur = t & 1, nxt = cur ^ 1;
            if (t + 1 < T) {
                int k0 = (t + 1) * BK;
                int r0 = bm + lm, r1 = bm + lm + 64;
                ra0 = (r0 < N_NODES) ? *(const float4*)(A + (size_t)r0 * K + k0 + lk) : z4;
                ra1 = (r1 < N_NODES) ? *(const float4*)(A + (size_t)r1 * K + k0 + lk) : z4;
                rb0 = *(const float4*)(W + (size_t)(bn + lm) * K + k0 + lk);
                rb1 = *(const float4*)(W + (size_t)(bn + lm + 64) * K + k0 + lk);
            }
#pragma unroll
            for (int k = 0; k < BK; k++) {
                float4 av0 = *(const float4*)&As[cur][k][ty * 8];
                float4 av1 = *(const float4*)&As[cur][k][ty * 8 + 4];
                float4 bv0 = *(const float4*)&Bs[cur][k][tx * 8];
                float4 bv1 = *(const float4*)&Bs[cur][k][tx * 8 + 4];
                ull b0 = pack2(bv0.x, bv0.y);
                ull b1 = pack2(bv0.z, bv0.w);
                ull b2 = pack2(bv1.x, bv1.y);
                ull b3 = pack2(bv1.z, bv1.w);
                ull ad;
                ad = pack2(av0.x, av0.x);
                acc[0][0] = fma2(ad, b0, acc[0][0]); acc[0][1] = fma2(ad, b1, acc[0][1]);
                acc[0][2] = fma2(ad, b2, acc[0][2]); acc[0][3] = fma2(ad, b3, acc[0][3]);
                ad = pack2(av0.y, av0.y);
                acc[1][0] = fma2(ad, b0, acc[1][0]); acc[1][1] = fma2(ad, b1, acc[1][1]);
                acc[1][2] = fma2(ad, b2, acc[1][2]); acc[1][3] = fma2(ad, b3, acc[1][3]);
                ad = pack2(av0.z, av0.z);
                acc[2][0] = fma2(ad, b0, acc[2][0]); acc[2][1] = fma2(ad, b1, acc[2][1]);
                acc[2][2] = fma2(ad, b2, acc[2][2]); acc[2][3] = fma2(ad, b3, acc[2][3]);
                ad = pack2(av0.w, av0.w);
                acc[3][0] = fma2(ad, b0, acc[3][0]); acc[3][1] = fma2(ad, b1, acc[3][1]);
                acc[3][2] = fma2(ad, b2, acc[3][2]); acc[3][3] = fma2(ad, b3, acc[3][3]);
                ad = pack2(av1.x, av1.x);
                acc[4][0] = fma2(ad, b0, acc[4][0]); acc[4][1] = fma2(ad, b1, acc[4][1]);
                acc[4][2] = fma2(ad, b2, acc[4][2]); acc[4][3] = fma2(ad, b3, acc[4][3]);
                ad = pack2(av1.y, av1.y);
                acc[5][0] = fma2(ad, b0, acc[5][0]); acc[5][1] = fma2(ad, b1, acc[5][1]);
                acc[5][2] = fma2(ad, b2, acc[5][2]); acc[5][3] = fma2(ad, b3, acc[5][3]);
                ad = pack2(av1.z, av1.z);
                acc[6][0] = fma2(ad, b0, acc[6][0]); acc[6][1] = fma2(ad, b1, acc[6][1]);
                acc[6][2] = fma2(ad, b2, acc[6][2]); acc[6][3] = fma2(ad, b3, acc[6][3]);
                ad = pack2(av1.w, av1.w);
                acc[7][0] = fma2(ad, b0, acc[7][0]); acc[7][1] = fma2(ad, b1, acc[7][1]);
                acc[7][2] = fma2(ad, b2, acc[7][2]); acc[7][3] = fma2(ad, b3, acc[7][3]);
            }
            if (t + 1 < T) {
                As[nxt][lk + 0][lm] = ra0.x; As[nxt][lk + 1][lm] = ra0.y;
                As[nxt][lk + 2][lm] = ra0.z; As[nxt][lk + 3][lm] = ra0.w;
                As[nxt][lk + 0][lm + 64] = ra1.x; As[nxt][lk + 1][lm + 64] = ra1.y;
                As[nxt][lk + 2][lm + 64] = ra1.z; As[nxt][lk + 3][lm + 64] = ra1.w;
                Bs[nxt][lk + 0][lm] = rb0.x; Bs[nxt][lk + 1][lm] = rb0.y;
                Bs[nxt][lk + 2][lm] = rb0.z; Bs[nxt][lk + 3][lm] = rb0.w;
                Bs[nxt][lk + 0][lm + 64] = rb1.x; Bs[nxt][lk + 1][lm + 64] = rb1.y;
                Bs[nxt][lk + 2][lm + 64] = rb1.z; Bs[nxt][lk + 3][lm + 64] = rb1.w;
            }
            __syncthreads();
        }
        __syncthreads();   // ensure smem free before next phase prologue
    }

    // epilogue: bias + relu, stores
    float4 bb0 = *(const float4*)(bias + bn + tx * 8);
    float4 bb1 = *(const float4*)(bias + bn + tx * 8 + 4);
#pragma unroll
    for (int i = 0; i < 8; i++) {
        int row = bm + ty * 8 + i;
        if (row < N_NODES) {
            float c0, c1, c2, c3, c4, c5, c6, c7;
            unpack2(acc[i][0], c0, c1);
            unpack2(acc[i][1], c2, c3);
            unpack2(acc[i][2], c4, c5);
            unpack2(acc[i][3], c6, c7);
            float4 o0, o1;
            o0.x = fmaxf(c0 + bb0.x, 0.f); o0.y = fmaxf(c1 + bb0.y, 0.f);
            o0.z = fmaxf(c2 + bb0.z, 0.f); o0.w = fmaxf(c3 + bb0.w, 0.f);
            o1.x = fmaxf(c4 + bb1.x, 0.f); o1.y = fmaxf(c5 + bb1.y, 0.f);
            o1.z = fmaxf(c6 + bb1.z, 0.f); o1.w = fmaxf(c7 + bb1.w, 0.f);
            float* cp = C + (size_t)row * D_HID + bn + tx * 8;
            *(float4*)cp = o0;
            *(float4*)(cp + 4) = o1;
        }
    }
}

// ---------------- fused mean-pool + FC + sigmoid (deterministic) ----------------
__global__ void poolfc_kernel(const float* __restrict__ h, const void* __restrict__ batch,
                              const float* __restrict__ Wfc, const float* __restrict__ bfc,
                              float* __restrict__ out) {
    int g = blockIdx.x;
    int t = threadIdx.x;

    int start, end;
    {
        int lo = 0, hi = N_NODES;
        while (lo < hi) { int mid = (lo + hi) >> 1; if (load_idx(batch, mid) < g) lo = mid + 1; else hi = mid; }
        start = lo;
        lo = start; hi = N_NODES;
        while (lo < hi) { int mid = (lo + hi) >> 1; if (load_idx(batch, mid) < g + 1) lo = mid + 1; else hi = mid; }
        end = lo;
    }

    float s = 0.f;
    for (int n = start; n < end; n++)
        s += h[(size_t)n * D_HID + t];
    float inv = 1.0f / fmaxf((float)(end - start), 1.0f);
    float p = s * inv;

    __shared__ float r0[256], r1[256];
    r0[t] = p * Wfc[t];
    r1[t] = p * Wfc[D_HID + t];
    __syncthreads();
    for (int off = 128; off > 0; off >>= 1) {
        if (t < off) { r0[t] += r0[t + off]; r1[t] += r1[t + off]; }
        __syncthreads();
    }
    if (t == 0) {
        out[g * 2 + 0] = 1.0f / (1.0f + expf(-(r0[0] + bfc[0])));
        out[g * 2 + 1] = 1.0f / (1.0f + expf(-(r1[0] + bfc[1])));
    }
}

// ---------------- launch ----------------
extern "C" void kernel_launch(void* const* d_in, const int* in_sizes, int n_in,
                              void* d_out, int out_size) {
    const float* x  = (const float*)d_in[0];
    const void*  ei = d_in[1];
    const void*  bt = d_in[2];
    int wbase = (n_in >= 12 && in_sizes[3] == 1) ? 4 : 3;
    const float* W1_root = (const float*)d_in[wbase + 0];
    const float* W1_rel  = (const float*)d_in[wbase + 1];
    const float* b1      = (const float*)d_in[wbase + 2];
    const float* W2_root = (const float*)d_in[wbase + 3];
    const float* W2_rel  = (const float*)d_in[wbase + 4];
    const float* b2      = (const float*)d_in[wbase + 5];
    const float* Wfc     = (const float*)d_in[wbase + 6];
    const float* bfc     = (const float*)d_in[wbase + 7];
    float* out = (float*)d_out;

    // CSR build (ints only, deterministic gather later)
    detect_kernel<<<1, 1>>>((const int*)ei);
    zero_cnt_kernel<<<200, 256>>>();
    hist_kernel<<<1024, 256>>>(ei);
    scan_blk_kernel<<<SCAN_B, 1024>>>();
    scan_top_kernel<<<1, 32>>>();
    scan_add_kernel<<<SCAN_B, 1024>>>();
    fill_kernel<<<1024, 256>>>(ei);

    // Layer 1
    gather_agg<D_IN><<<(N_NODES * 32 + 255) / 256, 256>>>(x, g_agg1);
    {
        dim3 grid((N_NODES + 127) / 128, D_HID / 128);
        gemm_dual_relu<D_IN><<<grid, 256>>>(x, W1_root, g_agg1, W1_rel, b1, g_h1);
    }

    // Layer 2
    gather_agg<D_HID><<<(N_NODES * 32 + 255) / 256, 256>>>(g_h1, g_agg2);
    {
        dim3 grid((N_NODES + 127) / 128, D_HID / 128);
        gemm_dual_relu<D_HID><<<grid, 256>>>(g_h1, W2_root, g_agg2, W2_rel, b2, g_h2);
    }

    // Pool + FC + sigmoid
    poolfc_kernel<<<N_GRAPHS, 256>>>(g_h2, bt, Wfc, bfc, out);
    (void)out_size;
}

// round 4
// speedup vs baseline: 1.1546x; 1.0327x over previous
#include <cuda_runtime.h>
#include <cstdint>

#define N_NODES  50000
#define N_EDGES  800000
#define D_IN     128
#define D_HID    256
#define N_GRAPHS 256

typedef unsigned long long ull;

// ---------------- scratch (device globals; no runtime allocation) ----------------
__device__ float g_agg1[N_NODES * D_IN];     // 25.6 MB
__device__ float g_h1  [N_NODES * D_HID];    // 51.2 MB
__device__ float g_agg2[N_NODES * D_HID];    // 51.2 MB
__device__ float g_h2  [N_NODES * D_HID];    // 51.2 MB
__device__ int   g_cnt [N_NODES];            // in-degree histogram
__device__ int   g_row [N_NODES + 1];        // CSR row pointers
__device__ int   g_cur [N_NODES];            // fill cursors
__device__ int   g_col [N_EDGES];            // CSR column (src) ids
__device__ int   g_bsum[64];                 // block partial sums for scan
__device__ int   g_idx64;                    // 1 if indices are int64, 0 if int32

// ---------------- packed f32x2 helpers ----------------
__device__ __forceinline__ ull pack2(float lo, float hi) {
    ull r;
    asm("mov.b64 %0, {%1, %2};" : "=l"(r) : "f"(lo), "f"(hi));
    return r;
}
__device__ __forceinline__ void unpack2(ull v, float& lo, float& hi) {
    asm("mov.b64 {%0, %1}, %2;" : "=f"(lo), "=f"(hi) : "l"(v));
}
__device__ __forceinline__ ull fma2(ull a, ull b, ull c) {
    ull r;
    asm("fma.rn.f32x2 %0, %1, %2, %3;" : "=l"(r) : "l"(a), "l"(b), "l"(c));
    return r;
}

// ---------------- prep: dtype detect + zero histogram ----------------
__global__ void prep_kernel(const int* __restrict__ ei) {
    int i = blockIdx.x * blockDim.x + threadIdx.x;
    if (i == 0) {
        int any = 0;
#pragma unroll
        for (int j = 1; j < 256; j += 2) any |= ei[j];
        g_idx64 = (any == 0) ? 1 : 0;
    }
    int stride = gridDim.x * blockDim.x;
    for (; i < N_NODES; i += stride) g_cnt[i] = 0;
}

__device__ __forceinline__ int load_idx_(const void* p, int i, int i64) {
    if (i64) return (int)((const long long*)p)[i];
    return ((const int*)p)[i];
}

// ---------------- CSR build ----------------
__global__ void hist_kernel(const void* __restrict__ ei) {
    int i64 = g_idx64;
    int i = blockIdx.x * blockDim.x + threadIdx.x;
    int stride = gridDim.x * blockDim.x;
    for (; i < N_EDGES; i += stride) {
        int d = load_idx_(ei, i + N_EDGES, i64);
        atomicAdd(&g_cnt[d], 1);
    }
}

#define SCAN_B 49   // ceil(50000/1024)
__global__ void scan_blk_kernel() {
    __shared__ int wsum[32];
    int b = blockIdx.x, t = threadIdx.x;
    int i = b * 1024 + t;
    int v = (i < N_NODES) ? g_cnt[i] : 0;
    int lane = t & 31, w = t >> 5;
    int s = v;
#pragma unroll
    for (int o = 1; o < 32; o <<= 1) {
        int u = __shfl_up_sync(0xffffffffu, s, o);
        if (lane >= o) s += u;
    }
    if (lane == 31) wsum[w] = s;
    __syncthreads();
    if (w == 0) {
        int ws = wsum[lane];
#pragma unroll
        for (int o = 1; o < 32; o <<= 1) {
            int u = __shfl_up_sync(0xffffffffu, ws, o);
            if (lane >= o) ws += u;
        }
        wsum[lane] = ws;
    }
    __syncthreads();
    int incl = s + (w > 0 ? wsum[w - 1] : 0);
    if (i < N_NODES) g_row[i] = incl - v;
    if (t == 1023) g_bsum[b] = incl;
}

__global__ void scan_top_kernel() {
    if (threadIdx.x == 0) {
        int run = 0;
        for (int b = 0; b < SCAN_B; b++) { int v = g_bsum[b]; g_bsum[b] = run; run += v; }
    }
}

__global__ void scan_add_kernel() {
    int b = blockIdx.x, t = threadIdx.x;
    int i = b * 1024 + t;
    if (i < N_NODES) {
        int r = g_row[i] + g_bsum[b];
        g_row[i] = r;
        g_cur[i] = r;
    }
    if (i == 0) g_row[N_NODES] = N_EDGES;
}

__global__ void fill_kernel(const void* __restrict__ ei) {
    int i64 = g_idx64;
    int i = blockIdx.x * blockDim.x + threadIdx.x;
    int stride = gridDim.x * blockDim.x;
    for (; i < N_EDGES; i += stride) {
        int s = load_idx_(ei, i, i64);
        int d = load_idx_(ei, i + N_EDGES, i64);
        int pos = atomicAdd(&g_cur[d], 1);
        g_col[pos] = s;
    }
}

// ---------------- deterministic gather aggregation ----------------
template<int D>
__global__ void gather_agg(const float* __restrict__ x, float* __restrict__ agg) {
    int warp = (blockIdx.x * blockDim.x + threadIdx.x) >> 5;
    if (warp >= N_NODES) return;
    int lane = threadIdx.x & 31;
    int beg = g_row[warp], end = g_row[warp + 1];
    constexpr int V = D / 128;
    float4 a[V];
#pragma unroll
    for (int v = 0; v < V; v++) a[v] = make_float4(0.f, 0.f, 0.f, 0.f);
    int p = beg;
    for (; p + 2 <= end; p += 2) {
        int s0 = g_col[p], s1 = g_col[p + 1];
        const float4* x0 = (const float4*)x + (size_t)s0 * (D / 4);
        const float4* x1 = (const float4*)x + (size_t)s1 * (D / 4);
        float4 v0[V], v1[V];
#pragma unroll
        for (int v = 0; v < V; v++) { v0[v] = x0[lane + v * 32]; v1[v] = x1[lane + v * 32]; }
#pragma unroll
        for (int v = 0; v < V; v++) {
            a[v].x += v0[v].x + v1[v].x; a[v].y += v0[v].y + v1[v].y;
            a[v].z += v0[v].z + v1[v].z; a[v].w += v0[v].w + v1[v].w;
        }
    }
    if (p < end) {
        int s0 = g_col[p];
        const float4* x0 = (const float4*)x + (size_t)s0 * (D / 4);
#pragma unroll
        for (int v = 0; v < V; v++) {
            float4 v0 = x0[lane + v * 32];
            a[v].x += v0.x; a[v].y += v0.y; a[v].z += v0.z; a[v].w += v0.w;
        }
    }
    float4* ap = (float4*)agg + (size_t)warp * (D / 4);
#pragma unroll
    for (int v = 0; v < V; v++) ap[lane + v * 32] = a[v];
}

// ---------------- GEMM phase: C (+)= A@W^T [+bias], optional relu ----------------
// BM=128, BN=128, BK=16, 256 threads, 8x8 microtile; f32x2 packed FMA.
// B microtile: thread covers n in [tx*4, tx*4+4) and [64+tx*4, 64+tx*4+4)
// (16B-stride LDS -> conflict-free per 8-lane phase).
#define PADW 132
template<int K, int PHASES, bool LOAD_C, bool HAS_BIAS, bool RELU>
__global__ __launch_bounds__(256) void gemm_phase(
    const float* __restrict__ A1, const float* __restrict__ W1,
    const float* __restrict__ A2, const float* __restrict__ W2,
    const float* __restrict__ bias, float* __restrict__ C) {
    constexpr int BK = 16;
    constexpr int T = K / BK;
    __shared__ float As[2][BK][PADW];
    __shared__ float Bs[2][BK][PADW];

    int tid = threadIdx.x;
    int tx = tid & 15;
    int ty = tid >> 4;
    int bm = blockIdx.x * 128;
    int bn = blockIdx.y * 128;

    int lm = tid >> 2;
    int lk = (tid & 3) * 4;

    ull acc[8][4];
#pragma unroll
    for (int i = 0; i < 8; i++)
#pragma unroll
        for (int j = 0; j < 4; j++) acc[i][j] = pack2(0.f, 0.f);

    const float4 z4 = make_float4(0.f, 0.f, 0.f, 0.f);

#pragma unroll 1
    for (int phase = 0; phase < PHASES; phase++) {
        const float* A = phase ? A2 : A1;
        const float* W = phase ? W2 : W1;

        float4 ra0, ra1, rb0, rb1;
        {
            int r0 = bm + lm, r1 = bm + lm + 64;
            ra0 = (r0 < N_NODES) ? *(const float4*)(A + (size_t)r0 * K + lk) : z4;
            ra1 = (r1 < N_NODES) ? *(const float4*)(A + (size_t)r1 * K + lk) : z4;
            rb0 = *(const float4*)(W + (size_t)(bn + lm) * K + lk);
            rb1 = *(const float4*)(W + (size_t)(bn + lm + 64) * K + lk);
            As[0][lk + 0][lm] = ra0.x; As[0][lk + 1][lm] = ra0.y;
            As[0][lk + 2][lm] = ra0.z; As[0][lk + 3][lm] = ra0.w;
            As[0][lk + 0][lm + 64] = ra1.x; As[0][lk + 1][lm + 64] = ra1.y;
            As[0][lk + 2][lm + 64] = ra1.z; As[0][lk + 3][lm + 64] = ra1.w;
            Bs[0][lk + 0][lm] = rb0.x; Bs[0][lk + 1][lm] = rb0.y;
            Bs[0][lk + 2][lm] = rb0.z; Bs[0][lk + 3][lm] = rb0.w;
            Bs[0][lk + 0][lm + 64] = rb1.x; Bs[0][lk + 1][lm + 64] = rb1.y;
            Bs[0][lk + 2][lm + 64] = rb1.z; Bs[0][lk + 3][lm + 64] = rb1.w;
        }
        __syncthreads();

#pragma unroll 1
        for (int t = 0; t < T; t++) {
            int cur = t & 1, nxt = cur ^ 1;
            if (t + 1 < T) {
                int k0 = (t + 1) * BK;
                int r0 = bm + lm, r1 = bm + lm + 64;
                ra0 = (r0 < N_NODES) ? *(const float4*)(A + (size_t)r0 * K + k0 + lk) : z4;
                ra1 = (r1 < N_NODES) ? *(const float4*)(A + (size_t)r1 * K + k0 + lk) : z4;
                rb0 = *(const float4*)(W + (size_t)(bn + lm) * K + k0 + lk);
                rb1 = *(const float4*)(W + (size_t)(bn + lm + 64) * K + k0 + lk);
            }
#pragma unroll
            for (int k = 0; k < BK; k++) {
                float4 av0 = *(const float4*)&As[cur][k][ty * 8];
                float4 av1 = *(const float4*)&As[cur][k][ty * 8 + 4];
                float4 bv0 = *(const float4*)&Bs[cur][k][tx * 4];
                float4 bv1 = *(const float4*)&Bs[cur][k][64 + tx * 4];
                ull b0 = pack2(bv0.x, bv0.y);
                ull b1 = pack2(bv0.z, bv0.w);
                ull b2 = pack2(bv1.x, bv1.y);
                ull b3 = pack2(bv1.z, bv1.w);
                ull ad;
                ad = pack2(av0.x, av0.x);
                acc[0][0] = fma2(ad, b0, acc[0][0]); acc[0][1] = fma2(ad, b1, acc[0][1]);
                acc[0][2] = fma2(ad, b2, acc[0][2]); acc[0][3] = fma2(ad, b3, acc[0][3]);
                ad = pack2(av0.y, av0.y);
                acc[1][0] = fma2(ad, b0, acc[1][0]); acc[1][1] = fma2(ad, b1, acc[1][1]);
                acc[1][2] = fma2(ad, b2, acc[1][2]); acc[1][3] = fma2(ad, b3, acc[1][3]);
                ad = pack2(av0.z, av0.z);
                acc[2][0] = fma2(ad, b0, acc[2][0]); acc[2][1] = fma2(ad, b1, acc[2][1]);
                acc[2][2] = fma2(ad, b2, acc[2][2]); acc[2][3] = fma2(ad, b3, acc[2][3]);
                ad = pack2(av0.w, av0.w);
                acc[3][0] = fma2(ad, b0, acc[3][0]); acc[3][1] = fma2(ad, b1, acc[3][1]);
                acc[3][2] = fma2(ad, b2, acc[3][2]); acc[3][3] = fma2(ad, b3, acc[3][3]);
                ad = pack2(av1.x, av1.x);
                acc[4][0] = fma2(ad, b0, acc[4][0]); acc[4][1] = fma2(ad, b1, acc[4][1]);
                acc[4][2] = fma2(ad, b2, acc[4][2]); acc[4][3] = fma2(ad, b3, acc[4][3]);
                ad = pack2(av1.y, av1.y);
                acc[5][0] = fma2(ad, b0, acc[5][0]); acc[5][1] = fma2(ad, b1, acc[5][1]);
                acc[5][2] = fma2(ad, b2, acc[5][2]); acc[5][3] = fma2(ad, b3, acc[5][3]);
                ad = pack2(av1.z, av1.z);
                acc[6][0] = fma2(ad, b0, acc[6][0]); acc[6][1] = fma2(ad, b1, acc[6][1]);
                acc[6][2] = fma2(ad, b2, acc[6][2]); acc[6][3] = fma2(ad, b3, acc[6][3]);
                ad = pack2(av1.w, av1.w);
                acc[7][0] = fma2(ad, b0, acc[7][0]); acc[7][1] = fma2(ad, b1, acc[7][1]);
                acc[7][2] = fma2(ad, b2, acc[7][2]); acc[7][3] = fma2(ad, b3, acc[7][3]);
            }
            if (t + 1 < T) {
                As[nxt][lk + 0][lm] = ra0.x; As[nxt][lk + 1][lm] = ra0.y;
                As[nxt][lk + 2][lm] = ra0.z; As[nxt][lk + 3][lm] = ra0.w;
                As[nxt][lk + 0][lm + 64] = ra1.x; As[nxt][lk + 1][lm + 64] = ra1.y;
                As[nxt][lk + 2][lm + 64] = ra1.z; As[nxt][lk + 3][lm + 64] = ra1.w;
                Bs[nxt][lk + 0][lm] = rb0.x; Bs[nxt][lk + 1][lm] = rb0.y;
                Bs[nxt][lk + 2][lm] = rb0.z; Bs[nxt][lk + 3][lm] = rb0.w;
                Bs[nxt][lk + 0][lm + 64] = rb1.x; Bs[nxt][lk + 1][lm + 64] = rb1.y;
                Bs[nxt][lk + 2][lm + 64] = rb1.z; Bs[nxt][lk + 3][lm + 64] = rb1.w;
            }
            __syncthreads();
        }
        __syncthreads();
    }

    // epilogue
    float4 bb0 = make_float4(0.f, 0.f, 0.f, 0.f), bb1 = bb0;
    if (HAS_BIAS) {
        bb0 = *(const float4*)(bias + bn + tx * 4);
        bb1 = *(const float4*)(bias + bn + 64 + tx * 4);
    }
#pragma unroll
    for (int i = 0; i < 8; i++) {
        int row = bm + ty * 8 + i;
        if (row < N_NODES) {
            float* cp0 = C + (size_t)row * D_HID + bn + tx * 4;
            float* cp1 = cp0 + 64;
            float c0, c1, c2, c3, c4, c5, c6, c7;
            unpack2(acc[i][0], c0, c1);
            unpack2(acc[i][1], c2, c3);
            unpack2(acc[i][2], c4, c5);
            unpack2(acc[i][3], c6, c7);
            float4 o0 = make_float4(c0 + bb0.x, c1 + bb0.y, c2 + bb0.z, c3 + bb0.w);
            float4 o1 = make_float4(c4 + bb1.x, c5 + bb1.y, c6 + bb1.z, c7 + bb1.w);
            if (LOAD_C) {
                float4 p0 = *(const float4*)cp0;
                float4 p1 = *(const float4*)cp1;
                o0.x += p0.x; o0.y += p0.y; o0.z += p0.z; o0.w += p0.w;
                o1.x += p1.x; o1.y += p1.y; o1.z += p1.z; o1.w += p1.w;
            }
            if (RELU) {
                o0.x = fmaxf(o0.x, 0.f); o0.y = fmaxf(o0.y, 0.f);
                o0.z = fmaxf(o0.z, 0.f); o0.w = fmaxf(o0.w, 0.f);
                o1.x = fmaxf(o1.x, 0.f); o1.y = fmaxf(o1.y, 0.f);
                o1.z = fmaxf(o1.z, 0.f); o1.w = fmaxf(o1.w, 0.f);
            }
            *(float4*)cp0 = o0;
            *(float4*)cp1 = o1;
        }
    }
}

// ---------------- fused mean-pool + FC + sigmoid (deterministic) ----------------
__global__ void poolfc_kernel(const float* __restrict__ h, const void* __restrict__ batch,
                              const float* __restrict__ Wfc, const float* __restrict__ bfc,
                              float* __restrict__ out) {
    int g = blockIdx.x;
    int t = threadIdx.x;
    int i64 = g_idx64;

    int start, end;
    {
        int lo = 0, hi = N_NODES;
        while (lo < hi) { int mid = (lo + hi) >> 1; if (load_idx_(batch, mid, i64) < g) lo = mid + 1; else hi = mid; }
        start = lo;
        lo = start; hi = N_NODES;
        while (lo < hi) { int mid = (lo + hi) >> 1; if (load_idx_(batch, mid, i64) < g + 1) lo = mid + 1; else hi = mid; }
        end = lo;
    }

    float s = 0.f;
    for (int n = start; n < end; n++)
        s += h[(size_t)n * D_HID + t];
    float inv = 1.0f / fmaxf((float)(end - start), 1.0f);
    float p = s * inv;

    __shared__ float r0[256], r1[256];
    r0[t] = p * Wfc[t];
    r1[t] = p * Wfc[D_HID + t];
    __syncthreads();
    for (int off = 128; off > 0; off >>= 1) {
        if (t < off) { r0[t] += r0[t + off]; r1[t] += r1[t + off]; }
        __syncthreads();
    }
    if (t == 0) {
        out[g * 2 + 0] = 1.0f / (1.0f + expf(-(r0[0] + bfc[0])));
        out[g * 2 + 1] = 1.0f / (1.0f + expf(-(r1[0] + bfc[1])));
    }
}

// ---------------- launch ----------------
extern "C" void kernel_launch(void* const* d_in, const int* in_sizes, int n_in,
                              void* d_out, int out_size) {
    const float* x  = (const float*)d_in[0];
    const void*  ei = d_in[1];
    const void*  bt = d_in[2];
    int wbase = (n_in >= 12 && in_sizes[3] == 1) ? 4 : 3;
    const float* W1_root = (const float*)d_in[wbase + 0];
    const float* W1_rel  = (const float*)d_in[wbase + 1];
    const float* b1      = (const float*)d_in[wbase + 2];
    const float* W2_root = (const float*)d_in[wbase + 3];
    const float* W2_rel  = (const float*)d_in[wbase + 4];
    const float* b2      = (const float*)d_in[wbase + 5];
    const float* Wfc     = (const float*)d_in[wbase + 6];
    const float* bfc     = (const float*)d_in[wbase + 7];
    float* out = (float*)d_out;

    dim3 ggrid((N_NODES + 127) / 128, D_HID / 128);

    // (1) prep  (2) hist  (3) scan_blk
    prep_kernel<<<200, 256>>>((const int*)ei);
    hist_kernel<<<1024, 256>>>(ei);
    scan_blk_kernel<<<SCAN_B, 1024>>>();

    // (4) layer-1 root GEMM (no CSR dependency) -> profiled launch
    gemm_phase<D_IN, 1, false, true, false><<<ggrid, 256>>>(
        x, W1_root, nullptr, nullptr, b1, g_h1);

    // (5,6,7) finish CSR
    scan_top_kernel<<<1, 32>>>();
    scan_add_kernel<<<SCAN_B, 1024>>>();
    fill_kernel<<<1024, 256>>>(ei);

    // (8) gather layer 1, (9) rel GEMM accumulate + relu
    gather_agg<D_IN><<<(N_NODES * 32 + 255) / 256, 256>>>(x, g_agg1);
    gemm_phase<D_IN, 1, true, false, true><<<ggrid, 256>>>(
        g_agg1, W1_rel, nullptr, nullptr, nullptr, g_h1);

    // (10) gather layer 2, (11) dual GEMM + bias + relu
    gather_agg<D_HID><<<(N_NODES * 32 + 255) / 256, 256>>>(g_h1, g_agg2);
    gemm_phase<D_HID, 2, false, true, true><<<ggrid, 256>>>(
        g_h1, W2_root, g_agg2, W2_rel, b2, g_h2);

    // (12) pool + FC + sigmoid
    poolfc_kernel<<<N_GRAPHS, 256>>>(g_h2, bt, Wfc, bfc, out);
    (void)out_size;
}